// round 17
// baseline (speedup 1.0000x reference)
#include <cuda_runtime.h>
#include <cuda_fp16.h>
#include <cstdint>

#define TOK   131072
#define CCH   256
#define SEQ   128
#define NSEQ  1024
#define NHEADS 8
#define EDIM  32

// fp16 weight buffers
__device__ __half g_wh[6 * 65536], g_wl[6 * 65536];   // Wq, Wk, Wv, Wscale, Wshift, Wout

extern __shared__ __align__(16) char smraw[];

// ---------------- helpers ----------------
__device__ __forceinline__ uint32_t smem_u32(const void* p) {
    uint32_t a;
    asm("{ .reg .u64 t; cvta.to.shared.u64 t, %1; cvt.u32.u64 %0, t; }" : "=r"(a) : "l"(p));
    return a;
}
__device__ __forceinline__ void ldsm4(uint32_t* r, uint32_t a) {
    asm volatile("ldmatrix.sync.aligned.m8n8.x4.shared.b16 {%0,%1,%2,%3}, [%4];"
        : "=r"(r[0]), "=r"(r[1]), "=r"(r[2]), "=r"(r[3]) : "r"(a));
}
__device__ __forceinline__ void ldsm4t(uint32_t* r, uint32_t a) {
    asm volatile("ldmatrix.sync.aligned.m8n8.x4.trans.shared.b16 {%0,%1,%2,%3}, [%4];"
        : "=r"(r[0]), "=r"(r[1]), "=r"(r[2]), "=r"(r[3]) : "r"(a));
}
__device__ __forceinline__ void mmaf16(float* d, const uint32_t* a, uint32_t b0, uint32_t b1) {
    asm volatile("mma.sync.aligned.m16n8k16.row.col.f32.f16.f16.f32 "
        "{%0,%1,%2,%3}, {%4,%5,%6,%7}, {%8,%9}, {%0,%1,%2,%3};"
        : "+f"(d[0]), "+f"(d[1]), "+f"(d[2]), "+f"(d[3])
        : "r"(a[0]), "r"(a[1]), "r"(a[2]), "r"(a[3]), "r"(b0), "r"(b1));
}
#define CP16(s, g) asm volatile("cp.async.cg.shared.global [%0], [%1], 16;" :: "r"(s), "l"(g))
#define CPCOMMIT() asm volatile("cp.async.commit_group;")
#define CPWAIT0()  asm volatile("cp.async.wait_group 0;")

struct H4 { uint2 hi, lo; };
__device__ __forceinline__ H4 splitf4(float4 v) {
    __half2 h0 = __floats2half2_rn(v.x, v.y);
    __half2 h1 = __floats2half2_rn(v.z, v.w);
    float2 f0 = __half22float2(h0), f1 = __half22float2(h1);
    __half2 l0 = __floats2half2_rn(v.x - f0.x, v.y - f0.y);
    __half2 l1 = __floats2half2_rn(v.z - f1.x, v.w - f1.y);
    H4 r;
    r.hi.x = *(uint32_t*)&h0; r.hi.y = *(uint32_t*)&h1;
    r.lo.x = *(uint32_t*)&l0; r.lo.y = *(uint32_t*)&l1;
    return r;
}
__device__ __forceinline__ void split2(float a, float b, uint32_t& hi, uint32_t& lo) {
    __half2 h = __floats2half2_rn(a, b);
    float2 f = __half22float2(h);
    __half2 l = __floats2half2_rn(a - f.x, b - f.y);
    hi = *(uint32_t*)&h; lo = *(uint32_t*)&l;
}

#define RSTR 80   // 32 halves (64B) padded to 80B -> conflict-free ldmatrix
__device__ __forceinline__ uint32_t fragA(uint32_t matbase, int row0, int kb, int lane) {
    return matbase + (uint32_t)(row0 + (lane & 15)) * RSTR
                   + (uint32_t)(kb * 32 + ((lane >> 4) << 4));
}
#define RSTR64 144  // 64 halves (128B) padded to 144B (9x16) -> conflict-free
__device__ __forceinline__ uint32_t fragA64(uint32_t matbase, int row0, int kb, int lane) {
    return matbase + (uint32_t)(row0 + (lane & 15)) * RSTR64
                   + (uint32_t)(kb * 32 + ((lane >> 4) << 4));
}

// ---------------------------------------------------------------------------
// Kernel 0: weight conversion only (tiny). hi/lo and hi-only variants.
// ---------------------------------------------------------------------------
__global__ __launch_bounds__(256) void conv_kernel(
    const float4* __restrict__ s, uint2* __restrict__ dh, uint2* __restrict__ dl, int n)
{
    for (int i = blockIdx.x * blockDim.x + threadIdx.x; i < n; i += gridDim.x * blockDim.x) {
        H4 h = splitf4(s[i]);
        dh[i] = h.hi; dl[i] = h.lo;
    }
}
__global__ __launch_bounds__(256) void conv_hi_kernel(
    const float4* __restrict__ s, uint2* __restrict__ dh, int n)
{
    for (int i = blockIdx.x * blockDim.x + threadIdx.x; i < n; i += gridDim.x * blockDim.x) {
        float4 v = s[i];
        __half2 h0 = __floats2half2_rn(v.x, v.y);
        __half2 h1 = __floats2half2_rn(v.z, v.w);
        dh[i] = make_uint2(*(uint32_t*)&h0, *(uint32_t*)&h1);
    }
}

// ---------------------------------------------------------------------------
// Kernel 1: FULLY FUSED projection + attention + out-projection partial.
// CTA = one sequence (blockIdx.y) x one head-pair (blockIdx.x).
// Phase 1: 5-tensor 2-term GEMM (validated). Phase 2: in-SMEM attention
// (validated). Phase 3: out partial = O[128x64] @ WoutSlice[256x64]^T (3-term)
// accumulated into d_out via fp32 atomicAdd (4 partials per sequence).
// GEMM buffers: XH 0, XL 10240, CH 20480, CL 30720, W t: 40960+t*5120 -> 66560 (x2)
// Attn tiles: head hh at hh*40960: QH 0, QL 10240, KH 20480, VH 30720
// Wout slice: WOH 81920 (256x144B), WOL 118784 -> 155648
// O tiles (post-attn, overwrite attn region): OH 0 (128x144B), OL 18432
// ---------------------------------------------------------------------------
#define PJ_BUF 66560
#define WOH 81920
#define WOL 118784
#define OL_OFF 18432
#define PROJ_SMEM 155648

__global__ __launch_bounds__(256, 1) void proj_attn_kernel(
    const float* __restrict__ X, const float* __restrict__ CTX,
    float* __restrict__ out)
{
    const int tid = threadIdx.x;
    const int wid = tid >> 5, lane = tid & 31;
    const int n0 = blockIdx.x * 64;
    const int m0 = blockIdx.y * 128;   // == t0 (sequence start)
    const uint32_t sbase = smem_u32(smraw);

    float4 rx[4], rc[4];
    auto ldgA = [&](int c) {
        const int k0 = c * 32;
        #pragma unroll
        for (int u = 0; u < 4; ++u) {
            int idx = tid + u*256;
            int r = idx >> 3, f = idx & 7;
            size_t gi = (size_t)(m0 + r)*CCH + k0 + f*4;
            rx[u] = *(const float4*)&X[gi];
            rc[u] = *(const float4*)&CTX[gi];
        }
    };
    auto stsA = [&](int b) {
        char* p = smraw + b * PJ_BUF;
        #pragma unroll
        for (int u = 0; u < 4; ++u) {
            int idx = tid + u*256;
            int r = idx >> 3, f = idx & 7;
            uint32_t off = (uint32_t)(r*RSTR + f*8);
            H4 hx = splitf4(rx[u]);
            *(uint2*)(p + off)         = hx.hi;
            *(uint2*)(p + 10240 + off) = hx.lo;
            H4 hc = splitf4(rc[u]);
            *(uint2*)(p + 20480 + off) = hc.hi;
            *(uint2*)(p + 30720 + off) = hc.lo;
        }
    };
    auto issueW = [&](int c, int b) {
        const int k0 = c * 32;
        const uint32_t sb = sbase + b * PJ_BUF;
        int r = tid >> 2, seg = tid & 3;
        uint32_t so = (uint32_t)(r*RSTR + seg*16);
        #pragma unroll
        for (int t = 0; t < 5; ++t) {
            const __half* src = g_wh + (size_t)t*65536
                              + (size_t)(n0 + r)*CCH + k0 + seg*8;
            CP16(sb + 40960 + t*5120 + so, src);
        }
    };

    float acc[5][2][4][4] = {};   // [tensor][mi][nj][4]
    const int wm = (wid >> 1) * 32;
    const int hh = wid & 1;       // head within pair (channel half)

    auto compute = [&](uint32_t sb) {
        const int wn = hh * 32;
        #pragma unroll
        for (int kb = 0; kb < 2; ++kb) {
            uint32_t axh[2][4], axl[2][4], ach[2][4], acl[2][4];
            #pragma unroll
            for (int mi = 0; mi < 2; ++mi) {
                ldsm4(axh[mi], fragA(sb,         wm + mi*16, kb, lane));
                ldsm4(axl[mi], fragA(sb + 10240, wm + mi*16, kb, lane));
                ldsm4(ach[mi], fragA(sb + 20480, wm + mi*16, kb, lane));
                ldsm4(acl[mi], fragA(sb + 30720, wm + mi*16, kb, lane));
            }
            #pragma unroll
            for (int t = 0; t < 5; ++t) {
                const uint32_t (*Ah)[4] = (t < 3) ? axh : ach;
                const uint32_t (*Al)[4] = (t < 3) ? axl : acl;
                #pragma unroll
                for (int nb = 0; nb < 2; ++nb) {
                    uint32_t bh[4];
                    ldsm4(bh, fragA(sb + 40960 + t*5120, wn + nb*16, kb, lane));
                    #pragma unroll
                    for (int mi = 0; mi < 2; ++mi)
                        #pragma unroll
                        for (int j = 0; j < 2; ++j) {
                            float* d = acc[t][mi][nb*2 + j];
                            mmaf16(d, Ah[mi], bh[j], bh[j+2]);
                            mmaf16(d, Al[mi], bh[j], bh[j+2]);
                        }
                }
            }
        }
    };

    // Prologue
    ldgA(0);
    issueW(0, 0); CPCOMMIT();
    stsA(0);
    CPWAIT0(); __syncthreads();

    #pragma unroll 1
    for (int c = 0; c < 8; ++c) {
        const int b  = c & 1;
        const int nb = b ^ 1;
        if (c < 7) { ldgA(c + 1); issueW(c + 1, nb); CPCOMMIT(); }
        compute(sbase + b * PJ_BUF);
        if (c < 7) {
            CPWAIT0();
            stsA(nb);
            __syncthreads();
        }
    }
    __syncthreads();   // all GEMM-buffer reads done

    // Issue Wout slice load (overlaps epilogue + attention). Region 81920..155648.
    {
        #pragma unroll
        for (int i = 0; i < 16; ++i) {
            int task = tid + i*256;              // 0..4095
            int tensor = task >> 11;             // 0=hi, 1=lo
            int within = task & 2047;
            int r = within >> 3, seg = within & 7;
            const __half* src = (tensor ? g_wl : g_wh) + (size_t)5*65536
                              + (size_t)r*CCH + n0 + seg*8;
            uint32_t dst = sbase + (tensor ? WOL : WOH) + (uint32_t)(r*RSTR64 + seg*16);
            CP16(dst, src);
        }
        CPCOMMIT();
    }

    // --- Epilogue: scale*x+shift; write q(hi/lo), k(hi), v(hi) to SMEM ---
    const int g = lane >> 2, tg = lane & 3;
    const uint32_t abase = sbase + hh * 40960;
    #pragma unroll
    for (int mi = 0; mi < 2; ++mi)
        #pragma unroll
        for (int nj = 0; nj < 4; ++nj)
            #pragma unroll
            for (int h2 = 0; h2 < 2; ++h2) {
                const int row = wm + mi*16 + g + h2*8;
                const int col = nj*8 + tg*2;
                const int i0 = h2*2;
                float sc0 = acc[3][mi][nj][i0],   sc1 = acc[3][mi][nj][i0+1];
                float sh0 = acc[4][mi][nj][i0],   sh1 = acc[4][mi][nj][i0+1];
                float q0 = fmaf(sc0, acc[0][mi][nj][i0], sh0), q1 = fmaf(sc1, acc[0][mi][nj][i0+1], sh1);
                float k0 = fmaf(sc0, acc[1][mi][nj][i0], sh0), k1 = fmaf(sc1, acc[1][mi][nj][i0+1], sh1);
                float v0 = fmaf(sc0, acc[2][mi][nj][i0], sh0), v1 = fmaf(sc1, acc[2][mi][nj][i0+1], sh1);
                uint32_t off = (uint32_t)(row*RSTR + col*2);
                uint32_t hi, lo;
                split2(q0, q1, hi, lo);
                *(uint32_t*)(smraw + (abase - sbase) + off)         = hi;
                *(uint32_t*)(smraw + (abase - sbase) + 10240 + off) = lo;
                split2(k0, k1, hi, lo);
                *(uint32_t*)(smraw + (abase - sbase) + 20480 + off) = hi;
                split2(v0, v1, hi, lo);
                *(uint32_t*)(smraw + (abase - sbase) + 30720 + off) = hi;
            }
    __syncthreads();

    // --- Attention: warp = (head hh, row stripe wm). S stripe 32x128. ---
    float p[2][16][4] = {};
    #pragma unroll
    for (int kb = 0; kb < 2; ++kb) {
        uint32_t aqh[2][4], aql[2][4];
        #pragma unroll
        for (int mi = 0; mi < 2; ++mi) {
            ldsm4(aqh[mi], fragA(abase,         wm + mi*16, kb, lane));
            ldsm4(aql[mi], fragA(abase + 10240, wm + mi*16, kb, lane));
        }
        #pragma unroll
        for (int nb = 0; nb < 8; ++nb) {
            uint32_t bkh[4];
            ldsm4(bkh, fragA(abase + 20480, nb*16, kb, lane));
            #pragma unroll
            for (int mi = 0; mi < 2; ++mi)
                #pragma unroll
                for (int j = 0; j < 2; ++j) {
                    float* d = p[mi][nb*2 + j];
                    mmaf16(d, aqh[mi], bkh[j], bkh[j+2]);
                    mmaf16(d, aql[mi], bkh[j], bkh[j+2]);
                }
        }
    }

    const float scl = 0.17677669529663688f;  // 1/sqrt(32)
    #pragma unroll
    for (int mi = 0; mi < 2; ++mi)
        #pragma unroll
        for (int nb = 0; nb < 16; ++nb)
            #pragma unroll
            for (int r = 0; r < 4; ++r)
                p[mi][nb][r] = __expf(p[mi][nb][r] * scl);

    #pragma unroll
    for (int mi = 0; mi < 2; ++mi)
        #pragma unroll
        for (int h2 = 0; h2 < 2; ++h2) {
            float s = 0.f;
            #pragma unroll
            for (int nb = 0; nb < 16; ++nb) s += p[mi][nb][h2*2] + p[mi][nb][h2*2+1];
            s += __shfl_xor_sync(0xffffffffu, s, 1);
            s += __shfl_xor_sync(0xffffffffu, s, 2);
            const float inv = 1.0f / s;
            #pragma unroll
            for (int nb = 0; nb < 16; ++nb) {
                p[mi][nb][h2*2]   *= inv;
                p[mi][nb][h2*2+1] *= inv;
            }
        }

    // SV: full K range per warp
    float o[2][4][4] = {};
    #pragma unroll
    for (int kk = 0; kk < 8; ++kk) {
        uint32_t ah[2][4], al[2][4];
        #pragma unroll
        for (int mi = 0; mi < 2; ++mi) {
            split2(p[mi][2*kk][0],   p[mi][2*kk][1],   ah[mi][0], al[mi][0]);
            split2(p[mi][2*kk][2],   p[mi][2*kk][3],   ah[mi][1], al[mi][1]);
            split2(p[mi][2*kk+1][0], p[mi][2*kk+1][1], ah[mi][2], al[mi][2]);
            split2(p[mi][2*kk+1][2], p[mi][2*kk+1][3], ah[mi][3], al[mi][3]);
        }
        uint32_t bh[2][4];
        #pragma unroll
        for (int ch = 0; ch < 2; ++ch) {
            uint32_t vaddr = abase + 30720
                + (uint32_t)(kk*16 + (lane & 15))*RSTR
                + (uint32_t)((lane >> 4) << 4) + (uint32_t)ch*32;
            ldsm4t(bh[ch], vaddr);
        }
        #pragma unroll
        for (int mi = 0; mi < 2; ++mi)
            #pragma unroll
            for (int ch = 0; ch < 2; ++ch)
                #pragma unroll
                for (int j = 0; j < 2; ++j) {
                    float* d = o[mi][ch*2 + j];
                    mmaf16(d, ah[mi], bh[ch][j*2], bh[ch][j*2+1]);
                    mmaf16(d, al[mi], bh[ch][j*2], bh[ch][j*2+1]);
                }
    }
    __syncthreads();   // all V reads done before O overwrites attn region

    // --- Store O (hi/lo) to SMEM: 128 rows x 64 cols, stride 144 ---
    #pragma unroll
    for (int mi = 0; mi < 2; ++mi)
        #pragma unroll
        for (int nj = 0; nj < 4; ++nj)
            #pragma unroll
            for (int h2 = 0; h2 < 2; ++h2) {
                int row = wm + mi*16 + g + h2*8;
                int col = hh*32 + nj*8 + tg*2;
                uint32_t off = (uint32_t)(row*RSTR64 + col*2);
                uint32_t hi, lo;
                split2(o[mi][nj][h2*2], o[mi][nj][h2*2+1], hi, lo);
                *(uint32_t*)(smraw + off)          = hi;   // OH
                *(uint32_t*)(smraw + OL_OFF + off) = lo;   // OL
            }
    CPWAIT0();          // Wout slice arrived
    __syncthreads();

    // --- Out partial: O[128x64] @ WoutSlice[256x64]^T (3-term), atomicAdd ---
    {
        float acc2[2][16][4] = {};
        const int wm2 = (wid >> 1) * 32;
        const int wn2 = (wid & 1) * 128;
        #pragma unroll
        for (int kb = 0; kb < 4; ++kb) {
            uint32_t ah2[2][4], al2[2][4];
            #pragma unroll
            for (int mi = 0; mi < 2; ++mi) {
                ldsm4(ah2[mi], fragA64(sbase,          wm2 + mi*16, kb, lane));
                ldsm4(al2[mi], fragA64(sbase + OL_OFF, wm2 + mi*16, kb, lane));
            }
            #pragma unroll
            for (int nb = 0; nb < 8; ++nb) {
                uint32_t bh[4], bl[4];
                ldsm4(bh, fragA64(sbase + WOH, wn2 + nb*16, kb, lane));
                ldsm4(bl, fragA64(sbase + WOL, wn2 + nb*16, kb, lane));
                #pragma unroll
                for (int mi = 0; mi < 2; ++mi)
                    #pragma unroll
                    for (int j = 0; j < 2; ++j) {
                        float* d = acc2[mi][nb*2 + j];
                        mmaf16(d, ah2[mi], bh[j], bh[j+2]);
                        mmaf16(d, al2[mi], bh[j], bh[j+2]);
                        mmaf16(d, ah2[mi], bl[j], bl[j+2]);
                    }
            }
        }
        #pragma unroll
        for (int mi = 0; mi < 2; ++mi)
            #pragma unroll
            for (int nj = 0; nj < 16; ++nj)
                #pragma unroll
                for (int h2 = 0; h2 < 2; ++h2) {
                    int row = m0 + wm2 + mi*16 + g + h2*8;
                    int col = wn2 + nj*8 + tg*2;
                    atomicAdd(&out[(size_t)row*CCH + col],     acc2[mi][nj][h2*2]);
                    atomicAdd(&out[(size_t)row*CCH + col + 1], acc2[mi][nj][h2*2+1]);
                }
    }
}

// ---------------------------------------------------------------------------
extern "C" void kernel_launch(void* const* d_in, const int* in_sizes, int n_in,
                              void* d_out, int out_size)
{
    (void)in_sizes; (void)n_in; (void)out_size;
    const float* X      = (const float*)d_in[0];
    const float* CTX    = (const float*)d_in[1];
    const float* Wq     = (const float*)d_in[2];
    const float* Wkv    = (const float*)d_in[3];
    const float* Wout   = (const float*)d_in[4];
    const float* Wscale = (const float*)d_in[5];
    const float* Wshift = (const float*)d_in[6];
    float* out = (float*)d_out;

    __half *wh, *wl;
    cudaGetSymbolAddress((void**)&wh, g_wh);
    cudaGetSymbolAddress((void**)&wl, g_wl);

    cudaFuncSetAttribute(proj_attn_kernel, cudaFuncAttributeMaxDynamicSharedMemorySize, PROJ_SMEM);

    cudaMemsetAsync(out, 0, (size_t)TOK * CCH * sizeof(float));

    conv_hi_kernel<<<64, 256>>>((const float4*)Wq,     (uint2*)(wh + 0*65536), 16384);
    conv_hi_kernel<<<128, 256>>>((const float4*)Wkv,   (uint2*)(wh + 1*65536), 32768);
    conv_hi_kernel<<<64, 256>>>((const float4*)Wscale, (uint2*)(wh + 3*65536), 16384);
    conv_hi_kernel<<<64, 256>>>((const float4*)Wshift, (uint2*)(wh + 4*65536), 16384);
    conv_kernel<<<64, 256>>>((const float4*)Wout,      (uint2*)(wh + 5*65536), (uint2*)(wl + 5*65536), 16384);

    proj_attn_kernel<<<dim3(4, 1024), 256, PROJ_SMEM>>>(X, CTX, out);
}